// round 10
// baseline (speedup 1.0000x reference)
#include <cuda_runtime.h>
#include <cuda_fp16.h>
#include <stdint.h>

#define B_  128
#define G_  20000
#define P_  4096
#define KT  32
#define NT  32
#define NCTA   (P_/NT)     // 128
#define NCHUNK (G_/KT)     // 625 exact
#define BN_EPS 1e-5f
#define THREADS 384        // 8 consumer warps + 4 producer warps

// dynamic smem layout
#define A_ROWB     80                   // 32 halves + 16B pad -> u32 stride 20, conflict-free
#define A_STAGE_B  (128*A_ROWB)         // 10240; ring of 4
#define WF32_BASE  (4*A_STAGE_B)        // 40960
#define WF32_ROWB  144                  // 32 floats + 16B pad -> conflict-free conv reads
#define WF32_ARR   (32*WF32_ROWB)       // 4608 per array
#define WF32_STAGE (3*WF32_ARR)         // Wk | mapp | Wa = 13824; ring of 4
#define WF16_BASE  (WF32_BASE + 4*WF32_STAGE)   // 96256
#define W_ARR_B    2560                 // fp16 [n][k] stride-20 array
#define WF16_STAGE (2*W_ARR_B)          // W + T; ring of 2
#define SMEM_DYN   (WF16_BASE + 2*WF16_STAGE + 256)   // ~104.3 KB
#define SHS 34                           // epilogue f32 row stride

// named barriers: READY parity {1,2}, DONE parity {3,4}, consumer-epilogue 5
#define BAR_SYNC(id, n)   asm volatile("bar.sync %0, %1;"   :: "r"(id), "r"(n) : "memory")
#define BAR_ARRIVE(id, n) asm volatile("bar.arrive %0, %1;" :: "r"(id), "r"(n) : "memory")

__device__ __half g_Ah[B_ * G_];
__device__ float g_dpart[B_ * NCTA];

__device__ __forceinline__ uint32_t smem_u32(const void* p) {
    uint32_t a;
    asm("{ .reg .u64 t; cvta.to.shared.u64 t, %1; cvt.u32.u64 %0, t; }"
        : "=r"(a) : "l"(p));
    return a;
}
#define CPA16(dst, src) \
    asm volatile("cp.async.cg.shared.global [%0], [%1], 16;" :: "r"(dst), "l"(src))
#define CPA_COMMIT() asm volatile("cp.async.commit_group;")
#define CPA_WAIT2()  asm volatile("cp.async.wait_group 2;")

__device__ __forceinline__ void mma_f16(float* d, const uint32_t* a, uint32_t b0, uint32_t b1) {
    asm volatile(
        "mma.sync.aligned.m16n8k16.row.col.f32.f16.f16.f32 "
        "{%0,%1,%2,%3}, {%4,%5,%6,%7}, {%8,%9}, {%0,%1,%2,%3};"
        : "+f"(d[0]), "+f"(d[1]), "+f"(d[2]), "+f"(d[3])
        : "r"(a[0]), "r"(a[1]), "r"(a[2]), "r"(a[3]), "r"(b0), "r"(b1));
}

// ---------------- pre-convert A: fp32 -> fp16 global ----------------
__global__ __launch_bounds__(256) void presplit_kernel(const float* __restrict__ A) {
    int i4 = blockIdx.x * 256 + threadIdx.x;   // 640000 float4s exactly
    float4 v = ((const float4*)A)[i4];
    __half2 h0 = __floats2half2_rn(v.x, v.y);
    __half2 h1 = __floats2half2_rn(v.z, v.w);
    ((uint2*)g_Ah)[i4] = make_uint2(*(uint32_t*)&h0, *(uint32_t*)&h1);
}

// ---------------- fused main kernel ----------------
__global__ __launch_bounds__(THREADS, 1) void bioxnet_fused_kernel(
    const float* __restrict__ mapp, const float* __restrict__ Wk,
    const float* __restrict__ Wa, const float* __restrict__ att_bias,
    const float* __restrict__ gamma, const float* __restrict__ beta,
    const float* __restrict__ dec_w,
    float* __restrict__ out_outcome, float* __restrict__ out_att)
{
    extern __shared__ __align__(16) char sp[];
    __shared__ float redS[8][NT], redQ[8][NT], s_mean[NT], s_rstd[NT];

    const int tid  = threadIdx.x;
    const int lane = tid & 31;
    const int wrp  = tid >> 5;
    const int col0 = blockIdx.x * NT;
    const uint32_t sb = smem_u32(sp);

    float accH[2][2][4], accT[2][2][4];
#pragma unroll
    for (int rt = 0; rt < 2; rt++)
#pragma unroll
        for (int nt = 0; nt < 2; nt++)
#pragma unroll
            for (int i = 0; i < 4; i++) { accH[rt][nt][i] = 0.f; accT[rt][nt][i] = 0.f; }

    if (tid >= 256) {
        // ================= PRODUCER: 4 warps =================
        const int pt = tid - 256;            // 0..127
        // A: thread -> row pt, 4x16B units
        const __half* gA = g_Ah + (long)pt * G_;
        const uint32_t adst = (uint32_t)(pt * A_ROWB);
        // W: thread -> k-row pt>>2, 2x16B units per array
        const int kr = pt >> 2;
        const int uu = (pt & 3) * 2;
        const long wgo = (long)kr * P_ + col0 + uu * 4;
        const uint32_t wdst = (uint32_t)(kr * WF32_ROWB + uu * 16);

#define CPA_A(chunk, st) do {                                            \
            uint32_t _b = sb + (uint32_t)(st) * A_STAGE_B + adst;        \
            const __half* _h = gA + (chunk) * KT;                        \
            CPA16(_b, _h);       CPA16(_b + 16, _h + 8);                 \
            CPA16(_b + 32, _h + 16); CPA16(_b + 48, _h + 24);            \
        } while (0)

#define CPA_W(chunk, st) do {                                              \
            uint32_t _b = sb + WF32_BASE + (uint32_t)(st) * WF32_STAGE + wdst; \
            long _g = (long)(chunk) * KT * P_ + wgo;                       \
            CPA16(_b,                Wk   + _g); CPA16(_b + 16,                Wk   + _g + 4); \
            CPA16(_b +   WF32_ARR,   mapp + _g); CPA16(_b + 16 +   WF32_ARR,   mapp + _g + 4); \
            CPA16(_b + 2*WF32_ARR,   Wa   + _g); CPA16(_b + 16 + 2*WF32_ARR,   Wa   + _g + 4); \
        } while (0)

        // conv: thread -> col wn, 4 k-pairs starting kq*4
        const int wn = pt & 31;
        const int kq = pt >> 5;   // 0..3

        CPA_A(0, 0); CPA_W(0, 0); CPA_COMMIT();
        CPA_A(1, 1); CPA_W(1, 1); CPA_COMMIT();

#pragma unroll 1
        for (int i = 0; i < NCHUNK; i++) {
            if (i >= 2) BAR_SYNC(3 + (i & 1), THREADS);  // consumers done with MMA(i-2)
            if (i + 2 < NCHUNK) { CPA_A(i + 2, (i + 2) & 3); CPA_W(i + 2, (i + 2) & 3); }
            CPA_COMMIT();
            CPA_WAIT2();                                  // chunk i fp32+A landed

            {   // convert chunk i -> fp16 stage i&1
                const float* f = (const float*)(sp + WF32_BASE + (i & 3) * WF32_STAGE);
                uint32_t* w = (uint32_t*)(sp + WF16_BASE + (i & 1) * WF16_STAGE);
                uint32_t* t = w + (W_ARR_B / 4);
#pragma unroll
                for (int j = 0; j < 4; j++) {
                    const int kp = kq * 4 + j;
                    const int k0 = 2 * kp;
                    float a0 = f[k0 * 36 + wn],        a1 = f[(k0 + 1) * 36 + wn];
                    float m0 = f[1152 + k0 * 36 + wn], m1 = f[1152 + (k0 + 1) * 36 + wn];
                    float b0 = f[2304 + k0 * 36 + wn], b1 = f[2304 + (k0 + 1) * 36 + wn];
                    __half2 pw = __floats2half2_rn(a0 * m0, a1 * m1);
                    __half2 pt2 = __floats2half2_rn(b0, b1);
                    w[wn * 20 + kp] = *(uint32_t*)&pw;
                    t[wn * 20 + kp] = *(uint32_t*)&pt2;
                }
            }
            BAR_ARRIVE(1 + (i & 1), THREADS);   // release: stage i ready
        }
    } else {
        // ================= CONSUMER: 8 warps =================
        const int gr = lane >> 2;   // 0..7
        const int tc = lane & 3;    // 0..3
        const int wr = wrp >> 1;    // 0..3: 32-row group
        const int wc = wrp & 1;     // 0..1: 16-col group

#pragma unroll 1
        for (int i = 0; i < NCHUNK; i++) {
            BAR_SYNC(1 + (i & 1), THREADS);     // acquire: stage i ready
            const uint32_t* aH = (const uint32_t*)(sp + (i & 3) * A_STAGE_B);
            const uint32_t* wW = (const uint32_t*)(sp + WF16_BASE + (i & 1) * WF16_STAGE);
            const uint32_t* wT = wW + (W_ARR_B / 4);
#pragma unroll
            for (int kh = 0; kh < 2; kh++) {
                uint32_t ah[2][4];
#pragma unroll
                for (int rt = 0; rt < 2; rt++) {
                    const int o = (wr * 32 + rt * 16 + gr) * 20 + kh * 8 + tc;
                    ah[rt][0] = aH[o];
                    ah[rt][1] = aH[o + 160];
                    ah[rt][2] = aH[o + 4];
                    ah[rt][3] = aH[o + 164];
                }
#pragma unroll
                for (int nt = 0; nt < 2; nt++) {
                    const int o = (wc * 16 + nt * 8 + gr) * 20 + kh * 8 + tc;
                    uint32_t w0 = wW[o], w1 = wW[o + 4];
                    uint32_t t0 = wT[o], t1 = wT[o + 4];
#pragma unroll
                    for (int rt = 0; rt < 2; rt++) {
                        mma_f16(accH[rt][nt], ah[rt], w0, w1);
                        mma_f16(accT[rt][nt], ah[rt], t0, t1);
                    }
                }
            }
            BAR_ARRIVE(3 + (i & 1), THREADS);   // stage i consumed
        }
    }
    __syncthreads();          // uniform: all 384 threads
    if (tid >= 256) return;   // producers exit; epilogue is consumer-only (named bar 5)

    // ---- spill accumulators (GEMM bias omitted: cancels in BN mean-subtract) ----
    const int gr = lane >> 2;
    const int tc = lane & 3;
    const int wr = wrp >> 1;
    const int wc = wrp & 1;
    float* sH = (float*)sp;
    float* sT = (float*)(sp + 17408);
#pragma unroll
    for (int rt = 0; rt < 2; rt++) {
#pragma unroll
        for (int nt = 0; nt < 2; nt++) {
            const int row0 = wr * 32 + rt * 16 + gr;
            const int col  = wc * 16 + nt * 8 + 2 * tc;
            *(float2*)&sH[(row0    ) * SHS + col] = make_float2(accH[rt][nt][0], accH[rt][nt][1]);
            *(float2*)&sH[(row0 + 8) * SHS + col] = make_float2(accH[rt][nt][2], accH[rt][nt][3]);
            *(float2*)&sT[(row0    ) * SHS + col] = make_float2(accT[rt][nt][0], accT[rt][nt][1]);
            *(float2*)&sT[(row0 + 8) * SHS + col] = make_float2(accT[rt][nt][2], accT[rt][nt][3]);
        }
    }
    BAR_SYNC(5, 256);

    // ---- batchnorm stats over all 128 rows (CTA-local) ----
    const int col = tid & 31;
    const int seg = tid >> 5;
    {
        float s = 0.f, q = 0.f;
#pragma unroll
        for (int r = 0; r < 16; r++) {
            float h = sH[(seg * 16 + r) * SHS + col];
            s += h; q += h * h;
        }
        redS[seg][col] = s;
        redQ[seg][col] = q;
    }
    BAR_SYNC(5, 256);
    if (tid < 32) {
        float ss = 0.f, qq = 0.f;
#pragma unroll
        for (int i = 0; i < 8; i++) { ss += redS[i][tid]; qq += redQ[i][tid]; }
        float mean = ss * (1.0f / B_);
        float var  = qq * (1.0f / B_) - mean * mean;
        s_mean[tid] = mean;
        s_rstd[tid] = rsqrtf(var + BN_EPS);
    }
    BAR_SYNC(5, 256);

    // ---- BN + tanh + sigmoid gate, outputs, decision partials ----
    const float mean = s_mean[col], rstd = s_rstd[col];
    const float gm = gamma[col0 + col], bt = beta[col0 + col];
    const float ab = att_bias[col0 + col], dw = dec_w[col0 + col];
#pragma unroll 4
    for (int r = 0; r < 16; r++) {
        int row = seg * 16 + r;
        float h  = sH[row * SHS + col];
        float hn = (h - mean) * rstd * gm + bt;
        float th = tanhf(hn);
        float z  = sT[row * SHS + col] + ab;
        float sg = 1.0f / (1.0f + __expf(-z));
        float o  = th * sg;
        long ofs = (long)row * P_ + col0 + col;
        out_outcome[ofs] = o;
        out_att[ofs]     = sg;
        float p = o * dw;
#pragma unroll
        for (int off = 16; off > 0; off >>= 1)
            p += __shfl_xor_sync(0xffffffffu, p, off);
        if (col == 0) g_dpart[row * NCTA + blockIdx.x] = p;
    }
}

__global__ __launch_bounds__(512) void bioxnet_decision_kernel(
    const float* __restrict__ dec_b, float* __restrict__ out_dec)
{
    __shared__ float red[4][B_];
    int t = threadIdx.x;
    int row = t >> 2;
    int seg = t & 3;
    const float4* p = (const float4*)(g_dpart + row * NCTA + seg * 32);
    float s = 0.f;
#pragma unroll
    for (int i = 0; i < 8; i++) {
        float4 v = p[i];
        s += v.x + v.y + v.z + v.w;
    }
    red[seg][row] = s;
    __syncthreads();
    if (t < B_) out_dec[t] = dec_b[0] + red[0][t] + red[1][t] + red[2][t] + red[3][t];
}

extern "C" void kernel_launch(void* const* d_in, const int* in_sizes, int n_in,
                              void* d_out, int out_size)
{
    (void)in_sizes; (void)n_in; (void)out_size;
    const float* A        = (const float*)d_in[0];
    const float* mapp     = (const float*)d_in[1];
    const float* Wk       = (const float*)d_in[2];
    // d_in[3] = bias: cancels exactly in batchnorm mean subtraction
    const float* Wa       = (const float*)d_in[4];
    const float* att_bias = (const float*)d_in[5];
    const float* gamma    = (const float*)d_in[6];
    const float* beta     = (const float*)d_in[7];
    const float* dec_w    = (const float*)d_in[8];
    const float* dec_b    = (const float*)d_in[9];

    float* out = (float*)d_out;
    float* out_outcome = out;
    float* out_dec     = out + (long)B_ * P_;
    float* out_att     = out + (long)B_ * P_ + B_;

    cudaFuncSetAttribute(bioxnet_fused_kernel,
                         cudaFuncAttributeMaxDynamicSharedMemorySize, SMEM_DYN);

    presplit_kernel<<<2500, 256>>>(A);
    bioxnet_fused_kernel<<<NCTA, THREADS, SMEM_DYN>>>(mapp, Wk, Wa, att_bias,
                                                      gamma, beta, dec_w,
                                                      out_outcome, out_att);
    bioxnet_decision_kernel<<<1, 512>>>(dec_b, out_dec);
}